// round 15
// baseline (speedup 1.0000x reference)
#include <cuda_runtime.h>
#include <cuda_fp16.h>
#include <cstdint>

#define B_    4096
#define D_    1024
#define NI    15
#define NL    16
#define NH    256
#define NC    100
#define HC    4096
#define EPSF  1e-10f

#define TILE_M 128
#define TILE_N 128
#define KCHUNK 64
#define NITER1 (D_ / KCHUNK)            // 16
#define NITER2 (HC / KCHUNK)            // 64 (full K for gemm2)
#define ABUF   (TILE_M * 128)
#define BBUF   (TILE_N * 128)
#define STAGE_BYTES (ABUF + BBUF)       // 32KB
#define NSTAGE 3
#define SMEM_TOTAL (NSTAGE * STAGE_BYTES) // 96KB dynamic (+8KB static sp)

#define GUM_CTAS   148
#define GUM_CHUNKS (NI * B_ / 8)        // 7680
#define GEMM_TILES 1024                 // 32 m-blocks x 32 n-tiles
#define NMB        (B_ / TILE_M)        // 32

// ---- scratch (device globals) ----
__device__ float g_split[NI * B_];
__device__ int   g_cnt1[NMB];           // gemm1 tile completions per m-block
__device__ int   g_cntg;                // gumbel CTA completions
__device__ float g_efl[NI * D_];
__device__ float g_c1[NI * D_];
__device__ __half g_xh[(size_t)B_ * D_];
__device__ __half g_wh[(size_t)HC * D_];
__device__ __half g_hs[(size_t)B_ * HC];
__device__ __half g_w2h[(size_t)128 * HC];

// ============================================================
// helpers
// ============================================================
__device__ __forceinline__ uint32_t smem_to_u32(const void* p) {
    uint32_t a;
    asm("{ .reg .u64 t; cvta.to.shared.u64 t, %1; cvt.u32.u64 %0, t; }" : "=r"(a) : "l"(p));
    return a;
}
__device__ __forceinline__ void cp_async16(uint32_t dst, const void* src) {
    asm volatile("cp.async.cg.shared.global [%0], [%1], 16;" :: "r"(dst), "l"(src));
}
__device__ __forceinline__ void cp_commit() { asm volatile("cp.async.commit_group;"); }
template<int N> __device__ __forceinline__ void cp_wait() {
    asm volatile("cp.async.wait_group %0;" :: "n"(N));
}
__device__ __forceinline__ void ldm_x4(uint32_t& r0, uint32_t& r1, uint32_t& r2, uint32_t& r3, uint32_t addr) {
    asm volatile("ldmatrix.sync.aligned.m8n8.x4.shared.b16 {%0,%1,%2,%3}, [%4];"
                 : "=r"(r0), "=r"(r1), "=r"(r2), "=r"(r3) : "r"(addr));
}
__device__ __forceinline__ void mma_fp16(float* d, const uint32_t* a, const uint32_t* b) {
    asm volatile("mma.sync.aligned.m16n8k16.row.col.f32.f16.f16.f32 "
                 "{%0,%1,%2,%3}, {%4,%5,%6,%7}, {%8,%9}, {%0,%1,%2,%3};"
                 : "+f"(d[0]), "+f"(d[1]), "+f"(d[2]), "+f"(d[3])
                 : "r"(a[0]), "r"(a[1]), "r"(a[2]), "r"(a[3]), "r"(b[0]), "r"(b[1]));
}
__device__ __forceinline__ float frcp(float x) {
    float r;
    asm("rcp.approx.f32 %0, %1;" : "=f"(r) : "f"(x));
    return r;
}
__device__ __forceinline__ uint32_t hscale(uint32_t a, __half2 s) {
    __half2 v = __hmul2(*(__half2*)&a, s);
    return *(uint32_t*)&v;
}

// ============================================================
// Kernel 0 (prep): conversions + tables + counter reset
// ============================================================
#define N4X (B_ * D_ / 4)
#define N4W (HC * D_ / 4)
#define N4P (128 * HC / 4)
#define N4F (NI * D_ / 4)
__global__ void k_prep(const float* __restrict__ x, const float* __restrict__ w,
                       const float* __restrict__ W2,
                       const float* __restrict__ fl, const float* __restrict__ fw) {
    int i = blockIdx.x * blockDim.x + threadIdx.x;
    if (blockIdx.x == 0) {
        if (threadIdx.x < NMB) g_cnt1[threadIdx.x] = 0;
        if (threadIdx.x == NMB) g_cntg = 0;
    }
    if (i < N4X) {
        float4 v = ((const float4*)x)[i];
        ((__half2*)g_xh)[2*i]   = __half2(__float2half_rn(v.x), __float2half_rn(v.y));
        ((__half2*)g_xh)[2*i+1] = __half2(__float2half_rn(v.z), __float2half_rn(v.w));
    } else if (i < N4X + N4W) {
        int j = i - N4X;
        float4 v = ((const float4*)w)[j];
        ((__half2*)g_wh)[2*j]   = __half2(__float2half_rn(v.x), __float2half_rn(v.y));
        ((__half2*)g_wh)[2*j+1] = __half2(__float2half_rn(v.z), __float2half_rn(v.w));
    } else if (i < N4X + N4W + N4P) {
        int j4 = i - N4X - N4W;
        int c  = j4 >> 10;
        int jj = (j4 & 1023) * 4;
        int l  = jj >> 8;
        int h  = jj & 255;
        float4 v = (c < NC) ? *(const float4*)&W2[((size_t)l * NC + c) * NH + h]
                            : make_float4(0.f, 0.f, 0.f, 0.f);
        ((__half2*)g_w2h)[(size_t)(c * HC + jj) / 2]     = __half2(__float2half_rn(v.x), __float2half_rn(v.y));
        ((__half2*)g_w2h)[(size_t)(c * HC + jj) / 2 + 1] = __half2(__float2half_rn(v.z), __float2half_rn(v.w));
    } else if (i < N4X + N4W + N4P + N4F) {
        int q = i - N4X - N4W - N4P;
        float4 f = ((const float4*)fl)[q];
        float4 w4 = ((const float4*)fw)[q];
        float4 e, c;
        e.x = __expf(f.x); e.y = __expf(f.y); e.z = __expf(f.z); e.w = __expf(f.w);
        c.x = e.x * w4.x;  c.y = e.y * w4.y;  c.z = e.z * w4.z;  c.w = e.w * w4.w;
        ((float4*)g_efl)[q] = e;
        ((float4*)g_c1)[q]  = c;
    }
}

// ============================================================
// shared HMMA machinery (8 warps, 64x32 warp tile)
// ============================================================
template<int LD>
__device__ __forceinline__ void stage_prefetch(uint32_t sbase, int stage,
                                               const __half* A, const __half* Bm,
                                               int m0, int n0, int k0, int tid) {
    uint32_t st = sbase + stage * STAGE_BYTES;
    int r  = tid >> 1;
    int cs = (tid & 1) * 4;
    const __half* sa = A  + (size_t)(m0 + r) * LD + k0;
    const __half* sb = Bm + (size_t)(n0 + r) * LD + k0;
    uint32_t rb_a = st + r * 128;
    uint32_t rb_b = st + ABUF + r * 128;
    #pragma unroll
    for (int c = cs; c < cs + 4; c++) {
        uint32_t phys = (uint32_t)(c ^ (r & 7)) * 16;
        cp_async16(rb_a + phys, sa + c * 8);
        cp_async16(rb_b + phys, sb + c * 8);
    }
}

// ============================================================
// fused kernel:
//   bid in [0, 148)   : persistent gumbel (grid-stride), signals g_cntg
//   bid in [148, 1172): GEMM1 tile -> g_hs; the LAST tile of each
//                       m-block continues in-place to run that
//                       m-block's FULL-K GEMM2 and writes out.
// ============================================================
__global__ void __launch_bounds__(256, 2) k_fused(const float* __restrict__ b1,
                                                  const float* __restrict__ b2,
                                                  const float* __restrict__ x,
                                                  const float* __restrict__ u,
                                                  const float* __restrict__ thr,
                                                  float* __restrict__ out) {
    extern __shared__ char smem[];
    __shared__ float sp[NL][TILE_M];
    __shared__ int lastflag;
    int tid = threadIdx.x;
    int wid = tid >> 5, lane = tid & 31;

    if (blockIdx.x < GUM_CTAS) {
        // ---------------- persistent gumbel ----------------
        for (int chunk = blockIdx.x; chunk < GUM_CHUNKS; chunk += GUM_CTAS) {
            int row = chunk * 8 + wid;
            int n = row / B_;
            int b = row - n * B_;
            const float4* u4 = (const float4*)(u + (size_t)row * D_);
            const float4* x4 = (const float4*)(x + (size_t)b   * D_);
            const float4* e4 = (const float4*)(g_efl + n * D_);
            const float4* c4 = (const float4*)(g_c1  + n * D_);

            float s0 = 0.f, s1 = 0.f;
            #pragma unroll
            for (int i = 0; i < 8; i++) {
                int idx = i * 32 + lane;
                float4 uv = u4[idx], xv = x4[idx], ev = e4[idx], cv = c4[idx];
                float r;
                r = frcp(-__logf(uv.x + EPSF) + EPSF); s0 = fmaf(ev.x, r, s0); s1 = fmaf(cv.x * xv.x, r, s1);
                r = frcp(-__logf(uv.y + EPSF) + EPSF); s0 = fmaf(ev.y, r, s0); s1 = fmaf(cv.y * xv.y, r, s1);
                r = frcp(-__logf(uv.z + EPSF) + EPSF); s0 = fmaf(ev.z, r, s0); s1 = fmaf(cv.z * xv.z, r, s1);
                r = frcp(-__logf(uv.w + EPSF) + EPSF); s0 = fmaf(ev.w, r, s0); s1 = fmaf(cv.w * xv.w, r, s1);
            }
            #pragma unroll
            for (int off = 16; off; off >>= 1) {
                s0 += __shfl_down_sync(0xffffffffu, s0, off);
                s1 += __shfl_down_sync(0xffffffffu, s1, off);
            }
            if (lane == 0) {
                float z = s1 / s0 - thr[n];
                g_split[row] = 1.f / (1.f + __expf(-z));
            }
        }
        __syncthreads();
        __threadfence();
        if (tid == 0) atomicAdd(&g_cntg, 1);
        return;
    }

    // ---------------- GEMM1 tile ----------------
    uint32_t sbase = smem_to_u32(smem);
    int bid2 = blockIdx.x - GUM_CTAS;
    int m_w = (wid & 1) * 64;
    int n_w = (wid >> 1) * 32;
    int mb = bid2 >> 5;
    int m0 = mb * TILE_M;
    int n0 = (bid2 & 31) * TILE_N;
    int trow = lane >> 2;
    int tcol = (lane & 3) * 2;

    {
        float acc[4][4][4] = {};

        stage_prefetch<D_>(sbase, 0, g_xh, g_wh, m0, n0, 0, tid);
        cp_commit();
        stage_prefetch<D_>(sbase, 1, g_xh, g_wh, m0, n0, KCHUNK, tid);
        cp_commit();
        stage_prefetch<D_>(sbase, 2, g_xh, g_wh, m0, n0, 2 * KCHUNK, tid);
        cp_commit();

        for (int i = 0; i < NITER1; i++) {
            int s = i % NSTAGE;
            cp_wait<2>();
            __syncthreads();

            uint32_t st = sbase + s * STAGE_BYTES;
            #pragma unroll
            for (int kk = 0; kk < 4; kk++) {
                int cbase = kk * 2;
                uint32_t ah[4][4], bh[4][2];
                #pragma unroll
                for (int mi = 0; mi < 4; mi++) {
                    int r = m_w + mi * 16 + (lane & 15);
                    uint32_t ch = (uint32_t)((cbase + (lane >> 4)) ^ (r & 7));
                    uint32_t off = (uint32_t)r * 128 + ch * 16;
                    ldm_x4(ah[mi][0], ah[mi][1], ah[mi][2], ah[mi][3], st + off);
                }
                #pragma unroll
                for (int nip = 0; nip < 2; nip++) {
                    int g = lane >> 3;
                    int r = n_w + (nip * 2 + (g >> 1)) * 8 + (lane & 7);
                    uint32_t ch = (uint32_t)((cbase + (g & 1)) ^ (r & 7));
                    uint32_t off = (uint32_t)r * 128 + ch * 16;
                    ldm_x4(bh[nip*2][0], bh[nip*2][1], bh[nip*2+1][0], bh[nip*2+1][1],
                           st + ABUF + off);
                }
                #pragma unroll
                for (int mi = 0; mi < 4; mi++)
                    #pragma unroll
                    for (int ni = 0; ni < 4; ni++)
                        mma_fp16(acc[mi][ni], ah[mi], bh[ni]);
            }
            __syncthreads();
            if (i + NSTAGE < NITER1)
                stage_prefetch<D_>(sbase, s, g_xh, g_wh, m0, n0, (i + NSTAGE) * KCHUNK, tid);
            cp_commit();
        }

        #pragma unroll
        for (int mi = 0; mi < 4; mi++) {
            int mA = m0 + m_w + mi * 16 + trow;
            int mB = mA + 8;
            #pragma unroll
            for (int ni = 0; ni < 4; ni++) {
                int n = n0 + n_w + ni * 8 + tcol;
                float bv0 = __ldg(&b1[n]), bv1 = __ldg(&b1[n + 1]);
                float v00 = fmaxf(acc[mi][ni][0] + bv0, 0.f);
                float v01 = fmaxf(acc[mi][ni][1] + bv1, 0.f);
                float v10 = fmaxf(acc[mi][ni][2] + bv0, 0.f);
                float v11 = fmaxf(acc[mi][ni][3] + bv1, 0.f);
                *(__half2*)&g_hs[(size_t)mA * HC + n] =
                    __half2(__float2half_rn(v00), __float2half_rn(v01));
                *(__half2*)&g_hs[(size_t)mB * HC + n] =
                    __half2(__float2half_rn(v10), __float2half_rn(v11));
            }
        }
    }

    // ---- last tile of this m-block continues into GEMM2 ----
    __syncthreads();
    __threadfence();
    if (tid == 0) {
        int old = atomicAdd(&g_cnt1[mb], 1);
        lastflag = (old == NMB - 1 + (32 - NMB));   // old == 31
        // wait for gumbel completion only if we are the continuation CTA
        if (lastflag)
            while (((volatile int*)&g_cntg)[0] < GUM_CTAS) __nanosleep(128);
    }
    __syncthreads();
    if (!lastflag) return;
    __threadfence();

    // ---- leaf probs for rows m0..m0+127 ----
    if (tid < TILE_M) {
        int b = m0 + tid;
        float s[NI];
        #pragma unroll
        for (int i = 0; i < NI; i++) s[i] = g_split[i * B_ + b];
        #pragma unroll
        for (int l = 0; l < NL; l++) {
            float p = 1.f;
            int pos = 0;
            #pragma unroll
            for (int k = 0; k < 4; k++) {
                int bit = (l >> (3 - k)) & 1;
                float sv = s[(1 << k) - 1 + pos];
                p *= bit ? sv : (1.f - sv);
                pos = 2 * pos + bit;
            }
            sp[l][tid] = p;
        }
    }

    // ---- GEMM2 over full K = 4096, N = 128 (100 used) ----
    float acc[4][4][4] = {};

    stage_prefetch<HC>(sbase, 0, g_hs, g_w2h, m0, 0, 0, tid);
    cp_commit();
    stage_prefetch<HC>(sbase, 1, g_hs, g_w2h, m0, 0, KCHUNK, tid);
    cp_commit();
    stage_prefetch<HC>(sbase, 2, g_hs, g_w2h, m0, 0, 2 * KCHUNK, tid);
    cp_commit();
    __syncthreads();   // sp ready

    for (int i = 0; i < NITER2; i++) {
        int s = i % NSTAGE;
        int leaf = i >> 2;          // 64-col chunks; 4 per 256-col leaf
        __half2 ph[4][2];
        #pragma unroll
        for (int mi = 0; mi < 4; mi++) {
            int rl = m_w + mi * 16 + trow;
            ph[mi][0] = __float2half2_rn(sp[leaf][rl]);
            ph[mi][1] = __float2half2_rn(sp[leaf][rl + 8]);
        }

        cp_wait<2>();
        __syncthreads();

        uint32_t st = sbase + s * STAGE_BYTES;
        #pragma unroll
        for (int kk = 0; kk < 4; kk++) {
            int cbase = kk * 2;
            uint32_t ah[4][4], bh[4][2];
            #pragma unroll
            for (int mi = 0; mi < 4; mi++) {
                int r = m_w + mi * 16 + (lane & 15);
                uint32_t ch = (uint32_t)((cbase + (lane >> 4)) ^ (r & 7));
                uint32_t off = (uint32_t)r * 128 + ch * 16;
                ldm_x4(ah[mi][0], ah[mi][1], ah[mi][2], ah[mi][3], st + off);
                ah[mi][0] = hscale(ah[mi][0], ph[mi][0]);
                ah[mi][1] = hscale(ah[mi][1], ph[mi][1]);
                ah[mi][2] = hscale(ah[mi][2], ph[mi][0]);
                ah[mi][3] = hscale(ah[mi][3], ph[mi][1]);
            }
            #pragma unroll
            for (int nip = 0; nip < 2; nip++) {
                int g = lane >> 3;
                int r = n_w + (nip * 2 + (g >> 1)) * 8 + (lane & 7);
                uint32_t ch = (uint32_t)((cbase + (g & 1)) ^ (r & 7));
                uint32_t off = (uint32_t)r * 128 + ch * 16;
                ldm_x4(bh[nip*2][0], bh[nip*2][1], bh[nip*2+1][0], bh[nip*2+1][1],
                       st + ABUF + off);
            }
            #pragma unroll
            for (int mi = 0; mi < 4; mi++)
                #pragma unroll
                for (int ni = 0; ni < 4; ni++)
                    mma_fp16(acc[mi][ni], ah[mi], bh[ni]);
        }
        __syncthreads();
        if (i + NSTAGE < NITER2)
            stage_prefetch<HC>(sbase, s, g_hs, g_w2h, m0, 0, (i + NSTAGE) * KCHUNK, tid);
        cp_commit();
    }

    // ---- epilogue: add leaf-weighted b2 bias, write out ----
    #pragma unroll
    for (int mi = 0; mi < 4; mi++) {
        int rA = m_w + mi * 16 + trow;
        int rB = rA + 8;
        int mA = m0 + rA;
        int mB = m0 + rB;
        #pragma unroll
        for (int ni = 0; ni < 4; ni++) {
            int n = n_w + ni * 8 + tcol;
            if (n < NC) {
                float biasA0 = 0.f, biasA1 = 0.f, biasB0 = 0.f, biasB1 = 0.f;
                #pragma unroll
                for (int l = 0; l < NL; l++) {
                    float bv0 = b2[l * NC + n];
                    float bv1 = b2[l * NC + n + 1];
                    biasA0 = fmaf(sp[l][rA], bv0, biasA0);
                    biasA1 = fmaf(sp[l][rA], bv1, biasA1);
                    biasB0 = fmaf(sp[l][rB], bv0, biasB0);
                    biasB1 = fmaf(sp[l][rB], bv1, biasB1);
                }
                *(float2*)&out[(size_t)mA * NC + n] =
                    make_float2(acc[mi][ni][0] + biasA0, acc[mi][ni][1] + biasA1);
                *(float2*)&out[(size_t)mB * NC + n] =
                    make_float2(acc[mi][ni][2] + biasB0, acc[mi][ni][3] + biasB1);
            }
        }
    }
}

extern "C" void kernel_launch(void* const* d_in, const int* in_sizes, int n_in,
                              void* d_out, int out_size) {
    const float* x   = (const float*)d_in[0];
    const float* u   = (const float*)d_in[1];
    const float* fl  = (const float*)d_in[2];
    const float* thr = (const float*)d_in[3];
    const float* fw  = (const float*)d_in[4];
    const float* W1  = (const float*)d_in[5];
    const float* b1  = (const float*)d_in[6];
    const float* W2  = (const float*)d_in[7];
    const float* b2  = (const float*)d_in[8];
    float* out = (float*)d_out;

    cudaFuncSetAttribute(k_fused, cudaFuncAttributeMaxDynamicSharedMemorySize, SMEM_TOTAL);

    k_prep<<<(N4X + N4W + N4P + N4F + 255) / 256, 256>>>(x, W1, W2, fl, fw);
    k_fused<<<GUM_CTAS + GEMM_TILES, 256, SMEM_TOTAL>>>(b1, b2, x, u, thr, out);
}

// round 16
// speedup vs baseline: 1.9019x; 1.9019x over previous
#include <cuda_runtime.h>
#include <cuda_fp16.h>
#include <cstdint>

#define B_    4096
#define D_    1024
#define NI    15
#define NL    16
#define NH    256
#define NC    100
#define HC    4096
#define EPSF  1e-10f

#define TILE_M 128
#define TILE_N 128
#define KCHUNK 64
#define NITER1 (D_ / KCHUNK)            // 16
#define KSPLIT2 8
#define KCH2   (HC / KSPLIT2)           // 512
#define NITER2 (KCH2 / KCHUNK)          // 8
#define ABUF   (TILE_M * 128)
#define BBUF   (TILE_N * 128)
#define STAGE_BYTES (ABUF + BBUF)       // 32KB
#define NSTAGE 3
#define SMEM_TOTAL (NSTAGE * STAGE_BYTES) // 96KB dynamic

#define GUM_CTAS   148
#define GUM_CHUNKS (NI * B_ / 16)       // 3840 chunks of 16 rows (2 rows/warp)
#define GEMM_TILES 1024                 // 32 x 32

// ---- scratch (device globals) ----
__device__ float g_split[NI * B_];
__device__ float g_part[KSPLIT2][(size_t)B_ * 128];
__device__ int   g_cnt[B_ / TILE_M];
__device__ float g_efl[NI * D_];
__device__ float g_c1[NI * D_];
__device__ __half g_xh[(size_t)B_ * D_];
__device__ __half g_wh[(size_t)HC * D_];
__device__ __half g_hs[(size_t)B_ * HC];
__device__ __half g_w2h[(size_t)128 * HC];

// ============================================================
// helpers
// ============================================================
__device__ __forceinline__ uint32_t smem_to_u32(const void* p) {
    uint32_t a;
    asm("{ .reg .u64 t; cvta.to.shared.u64 t, %1; cvt.u32.u64 %0, t; }" : "=r"(a) : "l"(p));
    return a;
}
__device__ __forceinline__ void cp_async16(uint32_t dst, const void* src) {
    asm volatile("cp.async.cg.shared.global [%0], [%1], 16;" :: "r"(dst), "l"(src));
}
__device__ __forceinline__ void cp_commit() { asm volatile("cp.async.commit_group;"); }
template<int N> __device__ __forceinline__ void cp_wait() {
    asm volatile("cp.async.wait_group %0;" :: "n"(N));
}
__device__ __forceinline__ void ldm_x4(uint32_t& r0, uint32_t& r1, uint32_t& r2, uint32_t& r3, uint32_t addr) {
    asm volatile("ldmatrix.sync.aligned.m8n8.x4.shared.b16 {%0,%1,%2,%3}, [%4];"
                 : "=r"(r0), "=r"(r1), "=r"(r2), "=r"(r3) : "r"(addr));
}
__device__ __forceinline__ void mma_fp16(float* d, const uint32_t* a, const uint32_t* b) {
    asm volatile("mma.sync.aligned.m16n8k16.row.col.f32.f16.f16.f32 "
                 "{%0,%1,%2,%3}, {%4,%5,%6,%7}, {%8,%9}, {%0,%1,%2,%3};"
                 : "+f"(d[0]), "+f"(d[1]), "+f"(d[2]), "+f"(d[3])
                 : "r"(a[0]), "r"(a[1]), "r"(a[2]), "r"(a[3]), "r"(b[0]), "r"(b[1]));
}
__device__ __forceinline__ float frcp(float x) {
    float r;
    asm("rcp.approx.f32 %0, %1;" : "=f"(r) : "f"(x));
    return r;
}
__device__ __forceinline__ uint32_t hscale(uint32_t a, __half2 s) {
    __half2 v = __hmul2(*(__half2*)&a, s);
    return *(uint32_t*)&v;
}
__device__ __forceinline__ float4 ldcs4(const float4* p) {
    return __ldcs(p);
}

// ============================================================
// Kernel 0 (prep): conversions + tables + counter reset
// ============================================================
#define N4X (B_ * D_ / 4)
#define N4W (HC * D_ / 4)
#define N4P (128 * HC / 4)
#define N4F (NI * D_ / 4)
__global__ void k_prep(const float* __restrict__ x, const float* __restrict__ w,
                       const float* __restrict__ W2,
                       const float* __restrict__ fl, const float* __restrict__ fw) {
    int i = blockIdx.x * blockDim.x + threadIdx.x;
    if (blockIdx.x == 0 && threadIdx.x < B_ / TILE_M) g_cnt[threadIdx.x] = 0;
    if (i < N4X) {
        float4 v = ((const float4*)x)[i];
        ((__half2*)g_xh)[2*i]   = __half2(__float2half_rn(v.x), __float2half_rn(v.y));
        ((__half2*)g_xh)[2*i+1] = __half2(__float2half_rn(v.z), __float2half_rn(v.w));
    } else if (i < N4X + N4W) {
        int j = i - N4X;
        float4 v = ((const float4*)w)[j];
        ((__half2*)g_wh)[2*j]   = __half2(__float2half_rn(v.x), __float2half_rn(v.y));
        ((__half2*)g_wh)[2*j+1] = __half2(__float2half_rn(v.z), __float2half_rn(v.w));
    } else if (i < N4X + N4W + N4P) {
        int j4 = i - N4X - N4W;
        int c  = j4 >> 10;
        int jj = (j4 & 1023) * 4;
        int l  = jj >> 8;
        int h  = jj & 255;
        float4 v = (c < NC) ? *(const float4*)&W2[((size_t)l * NC + c) * NH + h]
                            : make_float4(0.f, 0.f, 0.f, 0.f);
        ((__half2*)g_w2h)[(size_t)(c * HC + jj) / 2]     = __half2(__float2half_rn(v.x), __float2half_rn(v.y));
        ((__half2*)g_w2h)[(size_t)(c * HC + jj) / 2 + 1] = __half2(__float2half_rn(v.z), __float2half_rn(v.w));
    } else if (i < N4X + N4W + N4P + N4F) {
        int q = i - N4X - N4W - N4P;
        float4 f = ((const float4*)fl)[q];
        float4 w4 = ((const float4*)fw)[q];
        float4 e, c;
        e.x = __expf(f.x); e.y = __expf(f.y); e.z = __expf(f.z); e.w = __expf(f.w);
        c.x = e.x * w4.x;  c.y = e.y * w4.y;  c.z = e.z * w4.z;  c.w = e.w * w4.w;
        ((float4*)g_efl)[q] = e;
        ((float4*)g_c1)[q]  = c;
    }
}

// ============================================================
// shared HMMA machinery (8 warps, 64x32 warp tile)
// ============================================================
template<int LD>
__device__ __forceinline__ void stage_prefetch(uint32_t sbase, int stage,
                                               const __half* A, const __half* Bm,
                                               int m0, int n0, int k0, int tid) {
    uint32_t st = sbase + stage * STAGE_BYTES;
    int r  = tid >> 1;
    int cs = (tid & 1) * 4;
    const __half* sa = A  + (size_t)(m0 + r) * LD + k0;
    const __half* sb = Bm + (size_t)(n0 + r) * LD + k0;
    uint32_t rb_a = st + r * 128;
    uint32_t rb_b = st + ABUF + r * 128;
    #pragma unroll
    for (int c = cs; c < cs + 4; c++) {
        uint32_t phys = (uint32_t)(c ^ (r & 7)) * 16;
        cp_async16(rb_a + phys, sa + c * 8);
        cp_async16(rb_b + phys, sb + c * 8);
    }
}

// ============================================================
// fused kernel: bid < GUM_CTAS -> persistent gumbel (2 rows/warp)
//               else           -> GEMM1 tile
// ============================================================
__global__ void __launch_bounds__(256, 2) k_fused(const float* __restrict__ b1,
                                                  const float* __restrict__ x,
                                                  const float* __restrict__ u,
                                                  const float* __restrict__ thr) {
    extern __shared__ char smem[];
    int tid = threadIdx.x;
    int wid = tid >> 5, lane = tid & 31;

    if (blockIdx.x < GUM_CTAS) {
        // ------- persistent gumbel: each warp handles 2 adjacent rows -------
        for (int chunk = blockIdx.x; chunk < GUM_CHUNKS; chunk += GUM_CTAS) {
            int row0 = chunk * 16 + wid * 2;   // rows share node n (16-aligned)
            int row1 = row0 + 1;
            int n  = row0 / B_;
            int b0 = row0 - n * B_;
            int b1r = b0 + 1;
            const float4* ua = (const float4*)(u + (size_t)row0 * D_);
            const float4* ub = (const float4*)(u + (size_t)row1 * D_);
            const float4* xa = (const float4*)(x + (size_t)b0  * D_);
            const float4* xb = (const float4*)(x + (size_t)b1r * D_);
            const float4* e4 = (const float4*)(g_efl + n * D_);
            const float4* c4 = (const float4*)(g_c1  + n * D_);

            float s0a = 0.f, s1a = 0.f, s0b = 0.f, s1b = 0.f;
            #pragma unroll
            for (int i = 0; i < 8; i++) {
                int idx = i * 32 + lane;
                float4 uva = ldcs4(&ua[idx]);
                float4 uvb = ldcs4(&ub[idx]);
                float4 xva = xa[idx], xvb = xb[idx];
                float4 ev = e4[idx], cv = c4[idx];
                float r;
                r = frcp(-__logf(uva.x + EPSF) + EPSF); s0a = fmaf(ev.x, r, s0a); s1a = fmaf(cv.x * xva.x, r, s1a);
                r = frcp(-__logf(uvb.x + EPSF) + EPSF); s0b = fmaf(ev.x, r, s0b); s1b = fmaf(cv.x * xvb.x, r, s1b);
                r = frcp(-__logf(uva.y + EPSF) + EPSF); s0a = fmaf(ev.y, r, s0a); s1a = fmaf(cv.y * xva.y, r, s1a);
                r = frcp(-__logf(uvb.y + EPSF) + EPSF); s0b = fmaf(ev.y, r, s0b); s1b = fmaf(cv.y * xvb.y, r, s1b);
                r = frcp(-__logf(uva.z + EPSF) + EPSF); s0a = fmaf(ev.z, r, s0a); s1a = fmaf(cv.z * xva.z, r, s1a);
                r = frcp(-__logf(uvb.z + EPSF) + EPSF); s0b = fmaf(ev.z, r, s0b); s1b = fmaf(cv.z * xvb.z, r, s1b);
                r = frcp(-__logf(uva.w + EPSF) + EPSF); s0a = fmaf(ev.w, r, s0a); s1a = fmaf(cv.w * xva.w, r, s1a);
                r = frcp(-__logf(uvb.w + EPSF) + EPSF); s0b = fmaf(ev.w, r, s0b); s1b = fmaf(cv.w * xvb.w, r, s1b);
            }
            #pragma unroll
            for (int off = 16; off; off >>= 1) {
                s0a += __shfl_down_sync(0xffffffffu, s0a, off);
                s1a += __shfl_down_sync(0xffffffffu, s1a, off);
                s0b += __shfl_down_sync(0xffffffffu, s0b, off);
                s1b += __shfl_down_sync(0xffffffffu, s1b, off);
            }
            if (lane == 0) {
                float tn = thr[n];
                float za = s1a / s0a - tn;
                float zb = s1b / s0b - tn;
                g_split[row0] = 1.f / (1.f + __expf(-za));
                g_split[row1] = 1.f / (1.f + __expf(-zb));
            }
        }
        return;
    }

    // ---------------- GEMM1 path ----------------
    uint32_t sbase = smem_to_u32(smem);
    int bid2 = blockIdx.x - GUM_CTAS;
    int m_w = (wid & 1) * 64;
    int n_w = (wid >> 1) * 32;
    int m0 = (bid2 >> 5) * TILE_M;
    int n0 = (bid2 & 31) * TILE_N;

    float acc[4][4][4] = {};

    stage_prefetch<D_>(sbase, 0, g_xh, g_wh, m0, n0, 0, tid);
    cp_commit();
    stage_prefetch<D_>(sbase, 1, g_xh, g_wh, m0, n0, KCHUNK, tid);
    cp_commit();
    stage_prefetch<D_>(sbase, 2, g_xh, g_wh, m0, n0, 2 * KCHUNK, tid);
    cp_commit();

    for (int i = 0; i < NITER1; i++) {
        int s = i % NSTAGE;
        cp_wait<2>();
        __syncthreads();

        uint32_t st = sbase + s * STAGE_BYTES;
        #pragma unroll
        for (int kk = 0; kk < 4; kk++) {
            int cbase = kk * 2;
            uint32_t ah[4][4], bh[4][2];
            #pragma unroll
            for (int mi = 0; mi < 4; mi++) {
                int r = m_w + mi * 16 + (lane & 15);
                uint32_t ch = (uint32_t)((cbase + (lane >> 4)) ^ (r & 7));
                uint32_t off = (uint32_t)r * 128 + ch * 16;
                ldm_x4(ah[mi][0], ah[mi][1], ah[mi][2], ah[mi][3], st + off);
            }
            #pragma unroll
            for (int nip = 0; nip < 2; nip++) {
                int g = lane >> 3;
                int r = n_w + (nip * 2 + (g >> 1)) * 8 + (lane & 7);
                uint32_t ch = (uint32_t)((cbase + (g & 1)) ^ (r & 7));
                uint32_t off = (uint32_t)r * 128 + ch * 16;
                ldm_x4(bh[nip*2][0], bh[nip*2][1], bh[nip*2+1][0], bh[nip*2+1][1],
                       st + ABUF + off);
            }
            #pragma unroll
            for (int mi = 0; mi < 4; mi++)
                #pragma unroll
                for (int ni = 0; ni < 4; ni++)
                    mma_fp16(acc[mi][ni], ah[mi], bh[ni]);
        }
        __syncthreads();
        if (i + NSTAGE < NITER1)
            stage_prefetch<D_>(sbase, s, g_xh, g_wh, m0, n0, (i + NSTAGE) * KCHUNK, tid);
        cp_commit();
    }

    int trow = lane >> 2;
    int tcol = (lane & 3) * 2;
    #pragma unroll
    for (int mi = 0; mi < 4; mi++) {
        int mA = m0 + m_w + mi * 16 + trow;
        int mB = mA + 8;
        #pragma unroll
        for (int ni = 0; ni < 4; ni++) {
            int n = n0 + n_w + ni * 8 + tcol;
            float bv0 = __ldg(&b1[n]), bv1 = __ldg(&b1[n + 1]);
            float v00 = fmaxf(acc[mi][ni][0] + bv0, 0.f);
            float v01 = fmaxf(acc[mi][ni][1] + bv1, 0.f);
            float v10 = fmaxf(acc[mi][ni][2] + bv0, 0.f);
            float v11 = fmaxf(acc[mi][ni][3] + bv1, 0.f);
            *(__half2*)&g_hs[(size_t)mA * HC + n] =
                __half2(__float2half_rn(v00), __float2half_rn(v01));
            *(__half2*)&g_hs[(size_t)mB * HC + n] =
                __half2(__float2half_rn(v10), __float2half_rn(v11));
        }
    }
}

// ============================================================
// GEMM2: split-K with p folded into A frags (p computed in-kernel
// from g_split) + cooperative spin-wait reduction
// ============================================================
__global__ void __launch_bounds__(256, 2) k_gemm2(const float* __restrict__ b2,
                                                  float* __restrict__ out) {
    extern __shared__ char smem[];
    __shared__ float sp[NL][TILE_M];
    uint32_t sbase = smem_to_u32(smem);
    int tid = threadIdx.x;
    int wid = tid >> 5, lane = tid & 31;
    int m_w = (wid & 1) * 64;
    int n_w = (wid >> 1) * 32;
    int m0 = blockIdx.y * TILE_M;
    int kbase = blockIdx.x * KCH2;
    int trow = lane >> 2;

    if (tid < TILE_M) {
        int b = m0 + tid;
        float s[NI];
        #pragma unroll
        for (int i = 0; i < NI; i++) s[i] = g_split[i * B_ + b];
        #pragma unroll
        for (int l = 0; l < NL; l++) {
            float p = 1.f;
            int pos = 0;
            #pragma unroll
            for (int k = 0; k < 4; k++) {
                int bit = (l >> (3 - k)) & 1;
                float sv = s[(1 << k) - 1 + pos];
                p *= bit ? sv : (1.f - sv);
                pos = 2 * pos + bit;
            }
            sp[l][tid] = p;
        }
    }

    float acc[4][4][4] = {};

    stage_prefetch<HC>(sbase, 0, g_hs, g_w2h, m0, 0, kbase, tid);
    cp_commit();
    stage_prefetch<HC>(sbase, 1, g_hs, g_w2h, m0, 0, kbase + KCHUNK, tid);
    cp_commit();
    stage_prefetch<HC>(sbase, 2, g_hs, g_w2h, m0, 0, kbase + 2 * KCHUNK, tid);
    cp_commit();
    __syncthreads();

    for (int i = 0; i < NITER2; i++) {
        int s = i % NSTAGE;
        int leaf = (kbase + i * KCHUNK) >> 8;
        __half2 ph[4][2];
        #pragma unroll
        for (int mi = 0; mi < 4; mi++) {
            int rl = m_w + mi * 16 + trow;
            ph[mi][0] = __float2half2_rn(sp[leaf][rl]);
            ph[mi][1] = __float2half2_rn(sp[leaf][rl + 8]);
        }

        cp_wait<2>();
        __syncthreads();

        uint32_t st = sbase + s * STAGE_BYTES;
        #pragma unroll
        for (int kk = 0; kk < 4; kk++) {
            int cbase = kk * 2;
            uint32_t ah[4][4], bh[4][2];
            #pragma unroll
            for (int mi = 0; mi < 4; mi++) {
                int r = m_w + mi * 16 + (lane & 15);
                uint32_t ch = (uint32_t)((cbase + (lane >> 4)) ^ (r & 7));
                uint32_t off = (uint32_t)r * 128 + ch * 16;
                ldm_x4(ah[mi][0], ah[mi][1], ah[mi][2], ah[mi][3], st + off);
                ah[mi][0] = hscale(ah[mi][0], ph[mi][0]);
                ah[mi][1] = hscale(ah[mi][1], ph[mi][1]);
                ah[mi][2] = hscale(ah[mi][2], ph[mi][0]);
                ah[mi][3] = hscale(ah[mi][3], ph[mi][1]);
            }
            #pragma unroll
            for (int nip = 0; nip < 2; nip++) {
                int g = lane >> 3;
                int r = n_w + (nip * 2 + (g >> 1)) * 8 + (lane & 7);
                uint32_t ch = (uint32_t)((cbase + (g & 1)) ^ (r & 7));
                uint32_t off = (uint32_t)r * 128 + ch * 16;
                ldm_x4(bh[nip*2][0], bh[nip*2][1], bh[nip*2+1][0], bh[nip*2+1][1],
                       st + ABUF + off);
            }
            #pragma unroll
            for (int mi = 0; mi < 4; mi++)
                #pragma unroll
                for (int ni = 0; ni < 4; ni++)
                    mma_fp16(acc[mi][ni], ah[mi], bh[ni]);
        }
        __syncthreads();
        if (i + NSTAGE < NITER2)
            stage_prefetch<HC>(sbase, s, g_hs, g_w2h, m0, 0, kbase + (i + NSTAGE) * KCHUNK, tid);
        cp_commit();
    }

    int tcol = (lane & 3) * 2;
    float* part = g_part[blockIdx.x];
    #pragma unroll
    for (int mi = 0; mi < 4; mi++) {
        int mA = m0 + m_w + mi * 16 + trow;
        int mB = mA + 8;
        #pragma unroll
        for (int ni = 0; ni < 4; ni++) {
            int n = n_w + ni * 8 + tcol;
            *(float2*)&part[(size_t)mA * 128 + n] = make_float2(acc[mi][ni][0], acc[mi][ni][1]);
            *(float2*)&part[(size_t)mB * 128 + n] = make_float2(acc[mi][ni][2], acc[mi][ni][3]);
        }
    }

    __threadfence();
    if (tid == 0) {
        atomicAdd(&g_cnt[blockIdx.y], 1);
        while (((volatile int*)g_cnt)[blockIdx.y] < KSPLIT2) __nanosleep(64);
    }
    __syncthreads();
    __threadfence();

    int c0 = blockIdx.x * 13;
    int c1 = min(c0 + 13, NC);
    int ncols = c1 - c0;
    for (int idx = tid; idx < TILE_M * ncols; idx += 256) {
        int r = idx / ncols;
        int c = c0 + idx - r * ncols;
        int b = m0 + r;
        float v = 0.f;
        #pragma unroll
        for (int s = 0; s < KSPLIT2; s++) v += g_part[s][(size_t)b * 128 + c];
        float bias = 0.f;
        #pragma unroll
        for (int l = 0; l < NL; l++) bias += sp[l][r] * b2[l * NC + c];
        out[(size_t)b * NC + c] = v + bias;
    }
}

extern "C" void kernel_launch(void* const* d_in, const int* in_sizes, int n_in,
                              void* d_out, int out_size) {
    const float* x   = (const float*)d_in[0];
    const float* u   = (const float*)d_in[1];
    const float* fl  = (const float*)d_in[2];
    const float* thr = (const float*)d_in[3];
    const float* fw  = (const float*)d_in[4];
    const float* W1  = (const float*)d_in[5];
    const float* b1  = (const float*)d_in[6];
    const float* W2  = (const float*)d_in[7];
    const float* b2  = (const float*)d_in[8];
    float* out = (float*)d_out;

    cudaFuncSetAttribute(k_fused, cudaFuncAttributeMaxDynamicSharedMemorySize, SMEM_TOTAL);
    cudaFuncSetAttribute(k_gemm2, cudaFuncAttributeMaxDynamicSharedMemorySize, SMEM_TOTAL);

    k_prep<<<(N4X + N4W + N4P + N4F + 255) / 256, 256>>>(x, W1, W2, fl, fw);
    k_fused<<<GUM_CTAS + GEMM_TILES, 256, SMEM_TOTAL>>>(b1, x, u, thr);
    k_gemm2<<<dim3(KSPLIT2, B_ / TILE_M), 256, SMEM_TOTAL>>>(b2, out);
}

// round 17
// speedup vs baseline: 1.9060x; 1.0021x over previous
#include <cuda_runtime.h>
#include <cuda_fp16.h>
#include <cstdint>

#define B_    4096
#define D_    1024
#define NI    15
#define NL    16
#define NH    256
#define NC    100
#define HC    4096
#define EPSF  1e-10f

#define TILE_M 128
#define TILE_N 128
#define KCHUNK 64
#define NITER1 (D_ / KCHUNK)            // 16
#define KSPLIT2 8
#define KCH2   (HC / KSPLIT2)           // 512
#define NITER2 (KCH2 / KCHUNK)          // 8
#define ABUF   (TILE_M * 128)
#define BBUF   (TILE_N * 128)
#define STAGE_BYTES (ABUF + BBUF)       // 32KB
#define NSTAGE 3
#define SMEM_TOTAL (NSTAGE * STAGE_BYTES) // 96KB dynamic

#define GUM_CTAS   148
#define GUM_CHUNKS (NI * B_ / 16)       // 3840 chunks of 16 rows (2 rows/warp)
#define GEMM_TILES 1024                 // 32 x 32

// ---- scratch (device globals) ----
__device__ float g_split[NI * B_];
__device__ float g_part[KSPLIT2][(size_t)B_ * 128];
__device__ int   g_cnt[B_ / TILE_M];
__device__ __half2 g_ec[NI * D_];       // {exp(fl), exp(fl)*fw} packed fp16
__device__ __half g_xh[(size_t)B_ * D_];
__device__ __half g_wh[(size_t)HC * D_];
__device__ __half g_hs[(size_t)B_ * HC];
__device__ __half g_w2h[(size_t)128 * HC];

// ============================================================
// helpers
// ============================================================
__device__ __forceinline__ uint32_t smem_to_u32(const void* p) {
    uint32_t a;
    asm("{ .reg .u64 t; cvta.to.shared.u64 t, %1; cvt.u32.u64 %0, t; }" : "=r"(a) : "l"(p));
    return a;
}
__device__ __forceinline__ void cp_async16(uint32_t dst, const void* src) {
    asm volatile("cp.async.cg.shared.global [%0], [%1], 16;" :: "r"(dst), "l"(src));
}
__device__ __forceinline__ void cp_commit() { asm volatile("cp.async.commit_group;"); }
template<int N> __device__ __forceinline__ void cp_wait() {
    asm volatile("cp.async.wait_group %0;" :: "n"(N));
}
__device__ __forceinline__ void ldm_x4(uint32_t& r0, uint32_t& r1, uint32_t& r2, uint32_t& r3, uint32_t addr) {
    asm volatile("ldmatrix.sync.aligned.m8n8.x4.shared.b16 {%0,%1,%2,%3}, [%4];"
                 : "=r"(r0), "=r"(r1), "=r"(r2), "=r"(r3) : "r"(addr));
}
__device__ __forceinline__ void mma_fp16(float* d, const uint32_t* a, const uint32_t* b) {
    asm volatile("mma.sync.aligned.m16n8k16.row.col.f32.f16.f16.f32 "
                 "{%0,%1,%2,%3}, {%4,%5,%6,%7}, {%8,%9}, {%0,%1,%2,%3};"
                 : "+f"(d[0]), "+f"(d[1]), "+f"(d[2]), "+f"(d[3])
                 : "r"(a[0]), "r"(a[1]), "r"(a[2]), "r"(a[3]), "r"(b[0]), "r"(b[1]));
}
__device__ __forceinline__ float frcp(float x) {
    float r;
    asm("rcp.approx.f32 %0, %1;" : "=f"(r) : "f"(x));
    return r;
}
__device__ __forceinline__ uint32_t hscale(uint32_t a, __half2 s) {
    __half2 v = __hmul2(*(__half2*)&a, s);
    return *(uint32_t*)&v;
}
__device__ __forceinline__ float4 ldcs4(const float4* p) {
    return __ldcs(p);
}

// ============================================================
// Kernel 0 (prep): conversions + ec table + counter reset
// ============================================================
#define N4X (B_ * D_ / 4)
#define N4W (HC * D_ / 4)
#define N4P (128 * HC / 4)
#define N4F (NI * D_ / 4)
__global__ void k_prep(const float* __restrict__ x, const float* __restrict__ w,
                       const float* __restrict__ W2,
                       const float* __restrict__ fl, const float* __restrict__ fw) {
    int i = blockIdx.x * blockDim.x + threadIdx.x;
    if (blockIdx.x == 0 && threadIdx.x < B_ / TILE_M) g_cnt[threadIdx.x] = 0;
    if (i < N4X) {
        float4 v = ((const float4*)x)[i];
        ((__half2*)g_xh)[2*i]   = __half2(__float2half_rn(v.x), __float2half_rn(v.y));
        ((__half2*)g_xh)[2*i+1] = __half2(__float2half_rn(v.z), __float2half_rn(v.w));
    } else if (i < N4X + N4W) {
        int j = i - N4X;
        float4 v = ((const float4*)w)[j];
        ((__half2*)g_wh)[2*j]   = __half2(__float2half_rn(v.x), __float2half_rn(v.y));
        ((__half2*)g_wh)[2*j+1] = __half2(__float2half_rn(v.z), __float2half_rn(v.w));
    } else if (i < N4X + N4W + N4P) {
        int j4 = i - N4X - N4W;
        int c  = j4 >> 10;
        int jj = (j4 & 1023) * 4;
        int l  = jj >> 8;
        int h  = jj & 255;
        float4 v = (c < NC) ? *(const float4*)&W2[((size_t)l * NC + c) * NH + h]
                            : make_float4(0.f, 0.f, 0.f, 0.f);
        ((__half2*)g_w2h)[(size_t)(c * HC + jj) / 2]     = __half2(__float2half_rn(v.x), __float2half_rn(v.y));
        ((__half2*)g_w2h)[(size_t)(c * HC + jj) / 2 + 1] = __half2(__float2half_rn(v.z), __float2half_rn(v.w));
    } else if (i < N4X + N4W + N4P + N4F) {
        int q = i - N4X - N4W - N4P;
        float4 f = ((const float4*)fl)[q];
        float4 w4 = ((const float4*)fw)[q];
        float ex = __expf(f.x), ey = __expf(f.y), ez = __expf(f.z), ew = __expf(f.w);
        g_ec[q*4+0] = __halves2half2(__float2half_rn(ex), __float2half_rn(ex * w4.x));
        g_ec[q*4+1] = __halves2half2(__float2half_rn(ey), __float2half_rn(ey * w4.y));
        g_ec[q*4+2] = __halves2half2(__float2half_rn(ez), __float2half_rn(ez * w4.z));
        g_ec[q*4+3] = __halves2half2(__float2half_rn(ew), __float2half_rn(ew * w4.w));
    }
}

// ============================================================
// shared HMMA machinery (8 warps, 64x32 warp tile)
// ============================================================
template<int LD>
__device__ __forceinline__ void stage_prefetch(uint32_t sbase, int stage,
                                               const __half* A, const __half* Bm,
                                               int m0, int n0, int k0, int tid) {
    uint32_t st = sbase + stage * STAGE_BYTES;
    int r  = tid >> 1;
    int cs = (tid & 1) * 4;
    const __half* sa = A  + (size_t)(m0 + r) * LD + k0;
    const __half* sb = Bm + (size_t)(n0 + r) * LD + k0;
    uint32_t rb_a = st + r * 128;
    uint32_t rb_b = st + ABUF + r * 128;
    #pragma unroll
    for (int c = cs; c < cs + 4; c++) {
        uint32_t phys = (uint32_t)(c ^ (r & 7)) * 16;
        cp_async16(rb_a + phys, sa + c * 8);
        cp_async16(rb_b + phys, sb + c * 8);
    }
}

// ============================================================
// fused kernel: bid < GUM_CTAS -> persistent gumbel (2 rows/warp,
//               fp16 x + packed fp16 ec table: 10B/element)
//               else           -> GEMM1 tile
// ============================================================
__global__ void __launch_bounds__(256, 2) k_fused(const float* __restrict__ b1,
                                                  const float* __restrict__ u,
                                                  const float* __restrict__ thr) {
    extern __shared__ char smem[];
    int tid = threadIdx.x;
    int wid = tid >> 5, lane = tid & 31;

    if (blockIdx.x < GUM_CTAS) {
        for (int chunk = blockIdx.x; chunk < GUM_CHUNKS; chunk += GUM_CTAS) {
            int row0 = chunk * 16 + wid * 2;
            int row1 = row0 + 1;
            int n  = row0 / B_;
            int b0 = row0 - n * B_;
            const float4* ua = (const float4*)(u + (size_t)row0 * D_);
            const float4* ub = (const float4*)(u + (size_t)row1 * D_);
            const uint2*  xa = (const uint2*)(g_xh + (size_t)b0 * D_);
            const uint2*  xb = (const uint2*)(g_xh + (size_t)(b0 + 1) * D_);
            const float4* ec = (const float4*)(g_ec + n * D_);

            float s0a = 0.f, s1a = 0.f, s0b = 0.f, s1b = 0.f;
            #pragma unroll
            for (int i = 0; i < 8; i++) {
                int idx = i * 32 + lane;
                float4 uva = ldcs4(&ua[idx]);
                float4 uvb = ldcs4(&ub[idx]);
                uint2 xva = xa[idx], xvb = xb[idx];
                float4 ecv = ec[idx];
                __half2 x0a = *(__half2*)&xva.x, x1a = *(__half2*)&xva.y;
                __half2 x0b = *(__half2*)&xvb.x, x1b = *(__half2*)&xvb.y;
                __half2 ec0 = *(__half2*)&ecv.x, ec1 = *(__half2*)&ecv.y;
                __half2 ec2 = *(__half2*)&ecv.z, ec3 = *(__half2*)&ecv.w;
                float r, e, c;
                e = __low2float(ec0); c = __high2float(ec0);
                r = frcp(-__logf(uva.x + EPSF) + EPSF);
                s0a = fmaf(e, r, s0a); s1a = fmaf(c * __low2float(x0a), r, s1a);
                r = frcp(-__logf(uvb.x + EPSF) + EPSF);
                s0b = fmaf(e, r, s0b); s1b = fmaf(c * __low2float(x0b), r, s1b);
                e = __low2float(ec1); c = __high2float(ec1);
                r = frcp(-__logf(uva.y + EPSF) + EPSF);
                s0a = fmaf(e, r, s0a); s1a = fmaf(c * __high2float(x0a), r, s1a);
                r = frcp(-__logf(uvb.y + EPSF) + EPSF);
                s0b = fmaf(e, r, s0b); s1b = fmaf(c * __high2float(x0b), r, s1b);
                e = __low2float(ec2); c = __high2float(ec2);
                r = frcp(-__logf(uva.z + EPSF) + EPSF);
                s0a = fmaf(e, r, s0a); s1a = fmaf(c * __low2float(x1a), r, s1a);
                r = frcp(-__logf(uvb.z + EPSF) + EPSF);
                s0b = fmaf(e, r, s0b); s1b = fmaf(c * __low2float(x1b), r, s1b);
                e = __low2float(ec3); c = __high2float(ec3);
                r = frcp(-__logf(uva.w + EPSF) + EPSF);
                s0a = fmaf(e, r, s0a); s1a = fmaf(c * __high2float(x1a), r, s1a);
                r = frcp(-__logf(uvb.w + EPSF) + EPSF);
                s0b = fmaf(e, r, s0b); s1b = fmaf(c * __high2float(x1b), r, s1b);
            }
            #pragma unroll
            for (int off = 16; off; off >>= 1) {
                s0a += __shfl_down_sync(0xffffffffu, s0a, off);
                s1a += __shfl_down_sync(0xffffffffu, s1a, off);
                s0b += __shfl_down_sync(0xffffffffu, s0b, off);
                s1b += __shfl_down_sync(0xffffffffu, s1b, off);
            }
            if (lane == 0) {
                float tn = thr[n];
                float za = s1a / s0a - tn;
                float zb = s1b / s0b - tn;
                g_split[row0] = 1.f / (1.f + __expf(-za));
                g_split[row1] = 1.f / (1.f + __expf(-zb));
            }
        }
        return;
    }

    // ---------------- GEMM1 path ----------------
    uint32_t sbase = smem_to_u32(smem);
    int bid2 = blockIdx.x - GUM_CTAS;
    int m_w = (wid & 1) * 64;
    int n_w = (wid >> 1) * 32;
    int m0 = (bid2 >> 5) * TILE_M;
    int n0 = (bid2 & 31) * TILE_N;

    float acc[4][4][4] = {};

    stage_prefetch<D_>(sbase, 0, g_xh, g_wh, m0, n0, 0, tid);
    cp_commit();
    stage_prefetch<D_>(sbase, 1, g_xh, g_wh, m0, n0, KCHUNK, tid);
    cp_commit();
    stage_prefetch<D_>(sbase, 2, g_xh, g_wh, m0, n0, 2 * KCHUNK, tid);
    cp_commit();

    for (int i = 0; i < NITER1; i++) {
        int s = i % NSTAGE;
        cp_wait<2>();
        __syncthreads();

        uint32_t st = sbase + s * STAGE_BYTES;
        #pragma unroll
        for (int kk = 0; kk < 4; kk++) {
            int cbase = kk * 2;
            uint32_t ah[4][4], bh[4][2];
            #pragma unroll
            for (int mi = 0; mi < 4; mi++) {
                int r = m_w + mi * 16 + (lane & 15);
                uint32_t ch = (uint32_t)((cbase + (lane >> 4)) ^ (r & 7));
                uint32_t off = (uint32_t)r * 128 + ch * 16;
                ldm_x4(ah[mi][0], ah[mi][1], ah[mi][2], ah[mi][3], st + off);
            }
            #pragma unroll
            for (int nip = 0; nip < 2; nip++) {
                int g = lane >> 3;
                int r = n_w + (nip * 2 + (g >> 1)) * 8 + (lane & 7);
                uint32_t ch = (uint32_t)((cbase + (g & 1)) ^ (r & 7));
                uint32_t off = (uint32_t)r * 128 + ch * 16;
                ldm_x4(bh[nip*2][0], bh[nip*2][1], bh[nip*2+1][0], bh[nip*2+1][1],
                       st + ABUF + off);
            }
            #pragma unroll
            for (int mi = 0; mi < 4; mi++)
                #pragma unroll
                for (int ni = 0; ni < 4; ni++)
                    mma_fp16(acc[mi][ni], ah[mi], bh[ni]);
        }
        __syncthreads();
        if (i + NSTAGE < NITER1)
            stage_prefetch<D_>(sbase, s, g_xh, g_wh, m0, n0, (i + NSTAGE) * KCHUNK, tid);
        cp_commit();
    }

    int trow = lane >> 2;
    int tcol = (lane & 3) * 2;
    #pragma unroll
    for (int mi = 0; mi < 4; mi++) {
        int mA = m0 + m_w + mi * 16 + trow;
        int mB = mA + 8;
        #pragma unroll
        for (int ni = 0; ni < 4; ni++) {
            int n = n0 + n_w + ni * 8 + tcol;
            float bv0 = __ldg(&b1[n]), bv1 = __ldg(&b1[n + 1]);
            float v00 = fmaxf(acc[mi][ni][0] + bv0, 0.f);
            float v01 = fmaxf(acc[mi][ni][1] + bv1, 0.f);
            float v10 = fmaxf(acc[mi][ni][2] + bv0, 0.f);
            float v11 = fmaxf(acc[mi][ni][3] + bv1, 0.f);
            *(__half2*)&g_hs[(size_t)mA * HC + n] =
                __half2(__float2half_rn(v00), __float2half_rn(v01));
            *(__half2*)&g_hs[(size_t)mB * HC + n] =
                __half2(__float2half_rn(v10), __float2half_rn(v11));
        }
    }
}

// ============================================================
// GEMM2: split-K with p folded into A frags + cooperative reduce
// ============================================================
__global__ void __launch_bounds__(256, 2) k_gemm2(const float* __restrict__ b2,
                                                  float* __restrict__ out) {
    extern __shared__ char smem[];
    __shared__ float sp[NL][TILE_M];
    uint32_t sbase = smem_to_u32(smem);
    int tid = threadIdx.x;
    int wid = tid >> 5, lane = tid & 31;
    int m_w = (wid & 1) * 64;
    int n_w = (wid >> 1) * 32;
    int m0 = blockIdx.y * TILE_M;
    int kbase = blockIdx.x * KCH2;
    int trow = lane >> 2;

    if (tid < TILE_M) {
        int b = m0 + tid;
        float s[NI];
        #pragma unroll
        for (int i = 0; i < NI; i++) s[i] = g_split[i * B_ + b];
        #pragma unroll
        for (int l = 0; l < NL; l++) {
            float p = 1.f;
            int pos = 0;
            #pragma unroll
            for (int k = 0; k < 4; k++) {
                int bit = (l >> (3 - k)) & 1;
                float sv = s[(1 << k) - 1 + pos];
                p *= bit ? sv : (1.f - sv);
                pos = 2 * pos + bit;
            }
            sp[l][tid] = p;
        }
    }

    float acc[4][4][4] = {};

    stage_prefetch<HC>(sbase, 0, g_hs, g_w2h, m0, 0, kbase, tid);
    cp_commit();
    stage_prefetch<HC>(sbase, 1, g_hs, g_w2h, m0, 0, kbase + KCHUNK, tid);
    cp_commit();
    stage_prefetch<HC>(sbase, 2, g_hs, g_w2h, m0, 0, kbase + 2 * KCHUNK, tid);
    cp_commit();
    __syncthreads();

    for (int i = 0; i < NITER2; i++) {
        int s = i % NSTAGE;
        int leaf = (kbase + i * KCHUNK) >> 8;
        __half2 ph[4][2];
        #pragma unroll
        for (int mi = 0; mi < 4; mi++) {
            int rl = m_w + mi * 16 + trow;
            ph[mi][0] = __float2half2_rn(sp[leaf][rl]);
            ph[mi][1] = __float2half2_rn(sp[leaf][rl + 8]);
        }

        cp_wait<2>();
        __syncthreads();

        uint32_t st = sbase + s * STAGE_BYTES;
        #pragma unroll
        for (int kk = 0; kk < 4; kk++) {
            int cbase = kk * 2;
            uint32_t ah[4][4], bh[4][2];
            #pragma unroll
            for (int mi = 0; mi < 4; mi++) {
                int r = m_w + mi * 16 + (lane & 15);
                uint32_t ch = (uint32_t)((cbase + (lane >> 4)) ^ (r & 7));
                uint32_t off = (uint32_t)r * 128 + ch * 16;
                ldm_x4(ah[mi][0], ah[mi][1], ah[mi][2], ah[mi][3], st + off);
                ah[mi][0] = hscale(ah[mi][0], ph[mi][0]);
                ah[mi][1] = hscale(ah[mi][1], ph[mi][1]);
                ah[mi][2] = hscale(ah[mi][2], ph[mi][0]);
                ah[mi][3] = hscale(ah[mi][3], ph[mi][1]);
            }
            #pragma unroll
            for (int nip = 0; nip < 2; nip++) {
                int g = lane >> 3;
                int r = n_w + (nip * 2 + (g >> 1)) * 8 + (lane & 7);
                uint32_t ch = (uint32_t)((cbase + (g & 1)) ^ (r & 7));
                uint32_t off = (uint32_t)r * 128 + ch * 16;
                ldm_x4(bh[nip*2][0], bh[nip*2][1], bh[nip*2+1][0], bh[nip*2+1][1],
                       st + ABUF + off);
            }
            #pragma unroll
            for (int mi = 0; mi < 4; mi++)
                #pragma unroll
                for (int ni = 0; ni < 4; ni++)
                    mma_fp16(acc[mi][ni], ah[mi], bh[ni]);
        }
        __syncthreads();
        if (i + NSTAGE < NITER2)
            stage_prefetch<HC>(sbase, s, g_hs, g_w2h, m0, 0, kbase + (i + NSTAGE) * KCHUNK, tid);
        cp_commit();
    }

    int tcol = (lane & 3) * 2;
    float* part = g_part[blockIdx.x];
    #pragma unroll
    for (int mi = 0; mi < 4; mi++) {
        int mA = m0 + m_w + mi * 16 + trow;
        int mB = mA + 8;
        #pragma unroll
        for (int ni = 0; ni < 4; ni++) {
            int n = n_w + ni * 8 + tcol;
            *(float2*)&part[(size_t)mA * 128 + n] = make_float2(acc[mi][ni][0], acc[mi][ni][1]);
            *(float2*)&part[(size_t)mB * 128 + n] = make_float2(acc[mi][ni][2], acc[mi][ni][3]);
        }
    }

    __threadfence();
    if (tid == 0) {
        atomicAdd(&g_cnt[blockIdx.y], 1);
        while (((volatile int*)g_cnt)[blockIdx.y] < KSPLIT2) __nanosleep(64);
    }
    __syncthreads();
    __threadfence();

    int c0 = blockIdx.x * 13;
    int c1 = min(c0 + 13, NC);
    int ncols = c1 - c0;
    for (int idx = tid; idx < TILE_M * ncols; idx += 256) {
        int r = idx / ncols;
        int c = c0 + idx - r * ncols;
        int b = m0 + r;
        float v = 0.f;
        #pragma unroll
        for (int s = 0; s < KSPLIT2; s++) v += g_part[s][(size_t)b * 128 + c];
        float bias = 0.f;
        #pragma unroll
        for (int l = 0; l < NL; l++) bias += sp[l][r] * b2[l * NC + c];
        out[(size_t)b * NC + c] = v + bias;
    }
}

extern "C" void kernel_launch(void* const* d_in, const int* in_sizes, int n_in,
                              void* d_out, int out_size) {
    const float* x   = (const float*)d_in[0];
    const float* u   = (const float*)d_in[1];
    const float* fl  = (const float*)d_in[2];
    const float* thr = (const float*)d_in[3];
    const float* fw  = (const float*)d_in[4];
    const float* W1  = (const float*)d_in[5];
    const float* b1  = (const float*)d_in[6];
    const float* W2  = (const float*)d_in[7];
    const float* b2  = (const float*)d_in[8];
    float* out = (float*)d_out;

    cudaFuncSetAttribute(k_fused, cudaFuncAttributeMaxDynamicSharedMemorySize, SMEM_TOTAL);
    cudaFuncSetAttribute(k_gemm2, cudaFuncAttributeMaxDynamicSharedMemorySize, SMEM_TOTAL);

    k_prep<<<(N4X + N4W + N4P + N4F + 255) / 256, 256>>>(x, W1, W2, fl, fw);
    k_fused<<<GUM_CTAS + GEMM_TILES, 256, SMEM_TOTAL>>>(b1, u, thr);
    k_gemm2<<<dim3(KSPLIT2, B_ / TILE_M), 256, SMEM_TOTAL>>>(b2, out);
}